// round 16
// baseline (speedup 1.0000x reference)
#include <cuda_runtime.h>
#include <cstdint>

namespace {
constexpr int BATCH = 4096;
constexpr int SEQ   = 68;
constexpr int DIM   = 128;
constexpr int LRANK = 50;
constexpr int NT    = 256;     // two independent 128-thread halves
constexpr int HT    = 128;
constexpr int NSM   = 148;
constexpr int NHALF = 2 * NSM; // 296 independent batch streams
constexpr int ROWF4 = DIM / 4;
constexpr int BATF4 = SEQ * ROWF4;      // 2176 float4 per batch (= 128*17)
constexpr int BATFL = SEQ * DIM;        // 8704 floats per batch

// dynamic smem (float offsets): per-half double buffers + small scratch
constexpr int OFF_BUF = 0;                       // [2 halves][2 bufs][8704]
constexpr int OFF_P   = OFF_BUF + 4 * BATFL;     // [2][4][128] y partials
constexpr int OFF_Y   = OFF_P   + 2 * 4 * DIM;   // [2][128]
constexpr int OFF_O   = OFF_Y   + 2 * DIM;       // [2][128]
constexpr int OFF_W   = OFF_O   + 2 * DIM;       // 72 (w vector)
constexpr int SMEM_FLOATS = OFF_W + 72;
constexpr int SMEM_BYTES  = SMEM_FLOATS * 4;     // ~146 KB
}

#define DEVFN __device__ __forceinline__

// persistent scratch (device global — no allocation)
__device__ float g_Wc[DIM * DIM];   // Wc[e][c] = (Wo @ Wv)[e][c]

DEVFN void cp_async16(uint32_t smem_dst, const void* gptr) {
    asm volatile("cp.async.cg.shared.global [%0], [%1], 16;\n"
                 :: "r"(smem_dst), "l"(gptr) : "memory");
}
DEVFN void cp_commit() { asm volatile("cp.async.commit_group;" ::: "memory"); }
DEVFN void cp_wait1()  { asm volatile("cp.async.wait_group 1;"  ::: "memory"); }
DEVFN void half_bar(int id) {  // named barrier over this half's 128 threads
    asm volatile("bar.sync %0, 128;" :: "r"(id) : "memory");
}

// ---------------------------------------------------------------------------
// prep: Wc = Wo @ Wv, row-major (validated R10). 32 blocks x 256 threads.
// ---------------------------------------------------------------------------
__global__ void __launch_bounds__(256) prep_kernel(const float* __restrict__ Wv,
                                                   const float* __restrict__ Wo)
{
    const int t   = threadIdx.x;
    const int blk = blockIdx.x;
    __shared__ float sWo[DIM * 129];
    __shared__ float sWv[4][DIM];
    const float4* wo4 = reinterpret_cast<const float4*>(Wo);
    #pragma unroll
    for (int i = t; i < DIM * (DIM / 4); i += 256) {
        const float4 v = wo4[i];
        const int r = i >> 5, q = i & 31;
        float* dst = sWo + r * 129 + q * 4;
        dst[0] = v.x; dst[1] = v.y; dst[2] = v.z; dst[3] = v.w;
    }
    for (int k = t; k < 4 * DIM; k += 256) {
        const int j = k >> 7, d = k & 127;
        sWv[j][d] = Wv[d * DIM + 4 * blk + j];
    }
    __syncthreads();
    const int e    = t & 127;
    const int half = t >> 7;
    const float* row = sWo + e * 129;
    #pragma unroll
    for (int jj = 0; jj < 2; jj++) {
        const int cc = 2 * half + jj;
        float acc = 0.f;
        #pragma unroll 8
        for (int d = 0; d < DIM; d++) acc = fmaf(row[d], sWv[cc][d], acc);
        g_Wc[e * DIM + (4 * blk + cc)] = acc;
    }
}

// ---------------------------------------------------------------------------
// main: persistent; CTA = two INDEPENDENT 128-thread halves (named barriers).
// Each half streams its own batches:  y = sum_n w_n x[n,:];
// o = y @ Wc.T + bo;  out[n,:] = o.  Halves interleave their DRAM phases.
// ---------------------------------------------------------------------------
__global__ void __launch_bounds__(NT, 1)
linformer_persistent(const float* __restrict__ x,
                     const float* __restrict__ bo,
                     const float* __restrict__ F,
                     float* __restrict__ out)
{
    extern __shared__ float sm[];
    float* s_buf = sm + OFF_BUF;
    float* s_p   = sm + OFF_P;
    float* s_y   = sm + OFF_Y;
    float* s_o   = sm + OFF_O;
    float* s_w   = sm + OFF_W;

    const int t   = threadIdx.x;
    const int h   = t >> 7;          // which half (0/1)
    const int ht  = t & 127;         // thread id within half
    const int bar = 1 + h;           // named barrier id for this half
    const int hid = blockIdx.x * 2 + h;              // global half id 0..295
    const int nit = (BATCH - hid + NHALF - 1) / NHALF;  // 13 or 14 batches

    const uint32_t sbase = (uint32_t)__cvta_generic_to_shared(s_buf);
    float* s_ph = s_p + h * 4 * DIM;
    float* s_yh = s_y + h * DIM;
    float* s_oh = s_o + h * DIM;

    // issue prefetch of this half's batch `it` into its buffer (it&1)
    auto issue = [&](int it) {
        const size_t b = (size_t)hid + (size_t)NHALF * it;
        const float4* xb = reinterpret_cast<const float4*>(x + b * BATFL);
        const uint32_t dst = sbase + (uint32_t)(h * 2 + (it & 1)) * (BATFL * 4);
        #pragma unroll
        for (int k = 0; k < 17; k++) {          // 128*17 = 2176 exactly
            const int s = ht + HT * k;
            cp_async16(dst + s * 16, xb + s);
        }
        cp_commit();
    };

    issue(0);
    if (nit > 1) issue(1); else cp_commit();

    // full Wc row for output element e = ht (32 float4 = 128 regs)
    float4 wc[32];
    {
        const float4* wcp = reinterpret_cast<const float4*>(g_Wc + ht * DIM);
        #pragma unroll
        for (int k = 0; k < 32; k++) wc[k] = __ldg(wcp + k);
    }
    const float bor_e = __ldg(bo + ht);

    // w[n] = mean over l of F[n][l]  (sigma = 2^-68 -> fp32 softmax uniform)
    if (t < SEQ) {
        float s = 0.f;
        const float* fr = F + t * LRANK;
        #pragma unroll
        for (int l = 0; l < LRANK; l++) s += fr[l];
        s_w[t] = s * (1.0f / (float)LRANK);
    }
    __syncthreads();   // one-time: s_w visible to both halves

    const int chunk = ht & 31;        // float4 chunk of the 128-dim
    const int rg    = ht >> 5;        // row group 0..3; rows n = rg + 4k

    for (int it = 0; it < nit; ++it) {
        const float* bx = s_buf + (h * 2 + (it & 1)) * BATFL;

        cp_wait1();          // this half's batch resident (pending <= 1 group)
        half_bar(bar);

        // ---- y partials over rows n = rg + 4k  (17 rows each, exact) ----
        float4 acc = make_float4(0.f, 0.f, 0.f, 0.f);
        #pragma unroll
        for (int k = 0; k < 17; k++) {
            const int row = rg + 4 * k;
            const float wn = s_w[row];
            const float4 v = *reinterpret_cast<const float4*>(bx + row * DIM + chunk * 4);
            acc.x = fmaf(wn, v.x, acc.x); acc.y = fmaf(wn, v.y, acc.y);
            acc.z = fmaf(wn, v.z, acc.z); acc.w = fmaf(wn, v.w, acc.w);
        }
        *reinterpret_cast<float4*>(s_ph + rg * DIM + chunk * 4) = acc;
        half_bar(bar);       // buffer consumed; partials visible

        // refill this buffer for iteration it+2 (keeps DRAM fed)
        if (it + 2 < nit) issue(it + 2); else cp_commit();

        // ---- reduce y (one element per thread) ----
        s_yh[ht] = s_ph[ht] + s_ph[DIM + ht] + s_ph[2 * DIM + ht] + s_ph[3 * DIM + ht];
        half_bar(bar);

        // ---- direct GEMV: o[e] = bo[e] + sum_c y[c] * Wc[e][c]  ----
        // y read is a uniform broadcast (all threads same address).
        {
            const float4* y4 = reinterpret_cast<const float4*>(s_yh);
            float o = bor_e;
            #pragma unroll
            for (int k = 0; k < 32; k++) {
                const float4 yv = y4[k];
                const float4 w4 = wc[k];
                o = fmaf(yv.x, w4.x, o);
                o = fmaf(yv.y, w4.y, o);
                o = fmaf(yv.z, w4.z, o);
                o = fmaf(yv.w, w4.w, o);
            }
            s_oh[ht] = o;
        }
        half_bar(bar);

        // ---- broadcast-write: out[b][n][:] = o for all 68 rows ----
        const size_t b = (size_t)hid + (size_t)NHALF * it;
        float4* ob = reinterpret_cast<float4*>(out + b * BATFL);
        const float4 ov = *reinterpret_cast<const float4*>(s_oh + chunk * 4);
        #pragma unroll
        for (int k = 0; k < 17; k++) {
            __stcs(ob + ht + HT * k, ov);
        }
    }
}

extern "C" void kernel_launch(void* const* d_in, const int* in_sizes, int n_in,
                              void* d_out, int out_size)
{
    (void)in_sizes; (void)n_in; (void)out_size;
    const float* x  = (const float*)d_in[0];
    // d_in[1] = Wq (unused), d_in[2] = Wk (unused)
    const float* Wv = (const float*)d_in[3];
    const float* Wo = (const float*)d_in[4];
    const float* bo = (const float*)d_in[5];
    // d_in[6] = E (unused: sigma = 2^-68 makes the fp32 softmax exactly uniform)
    const float* F  = (const float*)d_in[7];
    float* out = (float*)d_out;

    prep_kernel<<<32, 256>>>(Wv, Wo);
    cudaFuncSetAttribute(linformer_persistent,
                         cudaFuncAttributeMaxDynamicSharedMemorySize, SMEM_BYTES);
    linformer_persistent<<<NSM, NT, SMEM_BYTES>>>(x, bo, F, out);
}